// round 7
// baseline (speedup 1.0000x reference)
#include <cuda_runtime.h>

// Ray marching with extended-space SDF, 2-layer MLP (3->128->1, softplus).
//
// Key transform: x = pivot + alpha*d  =>  h_pre[j] = c[j] + alpha * g[j]
//   c[j] = b1[j] + pivot . W1[:,j]      (per-problem, computed per CTA)
//   g[j] = d . W1[:,j]                  (per-ray, computed once, kept in regs)
// Work in log2 domain: y = x*log2(e); softplus(x) = ln2*(max(y,0)+log2(1+2^{-|y|}))
// Fold log2(e) into c,g and ln2 into W2 so the inner loop per hidden unit is:
//   1 FFMA + 1 EX2(MUFU) + 1 FADD + 1 LG2(MUFU) + 1 FMNMX + 1 FADD + 1 FFMA
//
// Thread layout: 4 threads per ray, each owns 32 hidden units (g in registers).
// Reduction across the 4 lanes via 2x shfl.xor. Dual accumulators halve the
// dependent-FFMA chain length.

#define RM_LOG2E 1.4426950408889634f
#define RM_LN2   0.6931471805599453f

__device__ __forceinline__ float rm_ex2(float x) {
    float r; asm("ex2.approx.ftz.f32 %0, %1;" : "=f"(r) : "f"(x)); return r;
}
__device__ __forceinline__ float rm_lg2(float x) {
    float r; asm("lg2.approx.f32 %0, %1;" : "=f"(r) : "f"(x)); return r;
}

__global__ __launch_bounds__(256)
void rm_kernel(const float4* __restrict__ r,
               const float*  __restrict__ pivot,
               const float*  __restrict__ W1,
               const float*  __restrict__ b1,
               const float*  __restrict__ W2,
               const float*  __restrict__ b2,
               const int*    __restrict__ n_iter_p,
               float*        __restrict__ out,
               int n_rays)
{
    __shared__ float  sW1[384];     // W1 row-major [3][128]
    __shared__ float2 sCW[128];     // interleaved: index k*4+sub -> {c', w2'}
    __shared__ float  sPivot[3];
    __shared__ float  sB2;

    const int tid = threadIdx.x;

    // Stage weights + pivot into shared
    for (int i = tid; i < 384; i += blockDim.x) sW1[i] = __ldg(&W1[i]);
    if (tid < 3)  sPivot[tid] = __ldg(&pivot[tid]);
    if (tid == 0) sB2 = __ldg(&b2[0]);
    __syncthreads();

    // c'[j] = (b1[j] + pivot . W1[:,j]) * log2e,  w2'[j] = W2[j] * ln2
    // Interleaved layout: lanes (sub=0..3) of a quarter-warp read 4
    // consecutive float2s -> conflict-free broadcast across the warp.
    if (tid < 128) {
        const int j = tid;
        float c = __ldg(&b1[j]);
        c = fmaf(sPivot[0], sW1[      j], c);
        c = fmaf(sPivot[1], sW1[128 + j], c);
        c = fmaf(sPivot[2], sW1[256 + j], c);
        const int sub = j >> 5, k = j & 31;
        sCW[k * 4 + sub] = make_float2(c * RM_LOG2E, __ldg(&W2[j]) * RM_LN2);
    }
    __syncthreads();

    const int gtid = blockIdx.x * blockDim.x + tid;
    const int ray  = gtid >> 2;
    const int sub  = gtid & 3;
    if (ray >= n_rays) return;

    // Ray, normalized over all 4 components
    const float4 rv = r[ray];
    const float inv = rsqrtf(rv.x*rv.x + rv.y*rv.y + rv.z*rv.z + rv.w*rv.w);
    const float rn0 = rv.x * inv;
    const float d0  = rv.y * inv;
    const float d1  = rv.z * inv;
    const float d2  = rv.w * inv;

    // Per-ray direction projection onto this thread's 32 hidden units,
    // pre-scaled by log2e. Lives entirely in registers.
    float g[32];
    const int jbase = sub * 32;
    #pragma unroll
    for (int k = 0; k < 32; ++k) {
        const int j = jbase + k;
        float gk = d0 * sW1[j];
        gk = fmaf(d1, sW1[128 + j], gk);
        gk = fmaf(d2, sW1[256 + j], gk);
        g[k] = gk * RM_LOG2E;
    }

    const float b2v = sB2;
    int niter = *n_iter_p;
    if (niter < 0 || niter > 4096) niter = 20;   // defensive vs dtype mismatch

    float alpha = 0.0f;
    for (int it = 0; it < niter; ++it) {
        float acc0 = 0.0f, acc1 = 0.0f;
        #pragma unroll
        for (int k = 0; k < 32; k += 2) {
            const float2 cwa = sCW[(k    ) * 4 + sub];
            const float2 cwb = sCW[(k + 1) * 4 + sub];

            const float ya = fmaf(alpha, g[k    ], cwa.x);  // x * log2e
            const float yb = fmaf(alpha, g[k + 1], cwb.x);

            const float ea = rm_ex2(-fabsf(ya));            // 2^{-|y|}
            const float eb = rm_ex2(-fabsf(yb));

            const float la = rm_lg2(1.0f + ea);             // log2(1+2^{-|y|})
            const float lb = rm_lg2(1.0f + eb);

            const float ha = fmaxf(ya, 0.0f) + la;          // softplus(x)/ln2
            const float hb = fmaxf(yb, 0.0f) + lb;

            acc0 = fmaf(ha, cwa.y, acc0);                   // * (W2*ln2)
            acc1 = fmaf(hb, cwb.y, acc1);
        }
        float acc = acc0 + acc1;
        // Sum the 4 partial accumulators of this ray's quarter-warp
        acc += __shfl_xor_sync(0xFFFFFFFFu, acc, 1);
        acc += __shfl_xor_sync(0xFFFFFFFFu, acc, 2);

        const float s   = acc + b2v;                        // sdf(x[1:])
        const float a   = fabsf(s);
        const float x0  = alpha * rn0;                      // x[0]
        const float ext = fmaxf(fmaxf(s, x0 - a), -(a + x0));
        alpha -= ext;
    }

    // res_x[:,1:] = pivot + alpha * d
    if (sub < 3) {
        const float dv = (sub == 0) ? d0 : (sub == 1 ? d1 : d2);
        out[ray * 3 + sub] = fmaf(alpha, dv, sPivot[sub]);
    }
}

extern "C" void kernel_launch(void* const* d_in, const int* in_sizes, int n_in,
                              void* d_out, int out_size)
{
    const float4* r     = (const float4*)d_in[0];   // (N, 4)
    const float*  pivot = (const float*)d_in[1];    // (1, 3)
    const float*  W1    = (const float*)d_in[2];    // (3, 128)
    const float*  b1    = (const float*)d_in[3];    // (128,)
    const float*  W2    = (const float*)d_in[4];    // (128, 1)
    const float*  b2    = (const float*)d_in[5];    // (1,)
    const int*    nit   = (const int*)d_in[6];      // scalar

    const int n_rays = in_sizes[0] / 4;
    float* out = (float*)d_out;                     // (N, 3)

    const int threads = 256;
    const int total   = n_rays * 4;
    const int blocks  = (total + threads - 1) / threads;
    rm_kernel<<<blocks, threads>>>(r, pivot, W1, b1, W2, b2, nit, out, n_rays);
}

// round 11
// speedup vs baseline: 1.1407x; 1.1407x over previous
#include <cuda_runtime.h>

// Ray marching with extended-space SDF, 2-layer MLP (3->128->1, softplus).
//
// x = pivot + alpha*d  =>  h_pre[j] = c[j] + alpha*g[j]  (affine in alpha)
// log2 domain: softplus(x)/ln2 = max(y,0) + log2(1+2^{-|y|}),  y = x*log2e
//
// R7 profile confirmed MUFU-bound (EX2+LG2 = 16 cyc/unit; issue=51.7%, fma=28.9%).
// This version removes LG2: log2(1+e) via degree-5 polynomial (A&S 4.1.43,
// |err|<=1e-5) evaluated 2-wide with fma.rn.f32x2, moving that work to the
// FMA pipe. New budget/unit: MUFU 8 cyc (EX2 only), FMA ~9 cyc.
//
// Layout: 4 threads per ray, each owns 32 hidden units (16 packed pairs).

#define RM_LOG2E 1.4426950408889634f
#define RM_LN2   0.6931471805599453f

// A&S 4.1.43 coefficients for ln(1+x), x in [0,1], scaled by log2(e):
#define RM_A1 1.44196727f
#define RM_A2 (-0.70967460f)
#define RM_A3 0.41762391f
#define RM_A4 (-0.19629705f)
#define RM_A5 0.04639483f

__device__ __forceinline__ float rm_ex2(float x) {
    float r; asm("ex2.approx.ftz.f32 %0, %1;" : "=f"(r) : "f"(x)); return r;
}
__device__ __forceinline__ unsigned long long rm_pack(float lo, float hi) {
    unsigned long long r;
    asm("mov.b64 %0, {%1, %2};" : "=l"(r) : "f"(lo), "f"(hi)); return r;
}
__device__ __forceinline__ void rm_unpack(unsigned long long v, float& lo, float& hi) {
    asm("mov.b64 {%0, %1}, %2;" : "=f"(lo), "=f"(hi) : "l"(v));
}
__device__ __forceinline__ unsigned long long rm_fma2(unsigned long long a,
                                                      unsigned long long b,
                                                      unsigned long long c) {
    unsigned long long d;
    asm("fma.rn.f32x2 %0, %1, %2, %3;" : "=l"(d) : "l"(a), "l"(b), "l"(c)); return d;
}
__device__ __forceinline__ unsigned long long rm_mul2(unsigned long long a,
                                                      unsigned long long b) {
    unsigned long long d;
    asm("mul.rn.f32x2 %0, %1, %2;" : "=l"(d) : "l"(a), "l"(b)); return d;
}
__device__ __forceinline__ unsigned long long rm_add2(unsigned long long a,
                                                      unsigned long long b) {
    unsigned long long d;
    asm("add.rn.f32x2 %0, %1, %2;" : "=l"(d) : "l"(a), "l"(b)); return d;
}

__global__ __launch_bounds__(256)
void rm_kernel(const float4* __restrict__ r,
               const float*  __restrict__ pivot,
               const float*  __restrict__ W1,
               const float*  __restrict__ b1,
               const float*  __restrict__ W2,
               const float*  __restrict__ b2,
               const int*    __restrict__ n_iter_p,
               float*        __restrict__ out,
               int n_rays)
{
    __shared__ float  sW1[384];     // W1 row-major [3][128]
    __shared__ float2 sCp2[64];     // c' pairs, interleaved: index p*4+sub
    __shared__ float2 sW2p2[64];    // w2' pairs, same layout (read as packed u64)
    __shared__ float  sPivot[3];
    __shared__ float  sB2;

    const int tid = threadIdx.x;

    for (int i = tid; i < 384; i += blockDim.x) sW1[i] = __ldg(&W1[i]);
    if (tid < 3)  sPivot[tid] = __ldg(&pivot[tid]);
    if (tid == 0) sB2 = __ldg(&b2[0]);
    __syncthreads();

    // c'[j] = (b1[j] + pivot.W1[:,j]) * log2e,  w2'[j] = W2[j] * ln2.
    // Pairwise interleaved layout: unit j = sub*32 + 2p + half lives at
    // element (p*4+sub), component half. Lanes sub=0..3 of a quarter-warp
    // read 4 consecutive float2s -> conflict-free broadcast.
    if (tid < 128) {
        const int j = tid;
        float c = __ldg(&b1[j]);
        c = fmaf(sPivot[0], sW1[      j], c);
        c = fmaf(sPivot[1], sW1[128 + j], c);
        c = fmaf(sPivot[2], sW1[256 + j], c);
        const int sub = j >> 5, m = j & 31, p = m >> 1, half = m & 1;
        ((float*)sCp2 )[(p * 4 + sub) * 2 + half] = c * RM_LOG2E;
        ((float*)sW2p2)[(p * 4 + sub) * 2 + half] = __ldg(&W2[j]) * RM_LN2;
    }
    __syncthreads();

    const int gtid = blockIdx.x * blockDim.x + tid;
    const int ray  = gtid >> 2;
    const int sub  = gtid & 3;
    if (ray >= n_rays) return;

    const float4 rv = r[ray];
    const float inv = rsqrtf(rv.x*rv.x + rv.y*rv.y + rv.z*rv.z + rv.w*rv.w);
    const float rn0 = rv.x * inv;
    const float d0  = rv.y * inv;
    const float d1  = rv.z * inv;
    const float d2  = rv.w * inv;

    // Per-ray direction projection for this thread's 32 units (pre-scaled).
    float g[32];
    const int jbase = sub * 32;
    #pragma unroll
    for (int k = 0; k < 32; ++k) {
        const int j = jbase + k;
        float gk = d0 * sW1[j];
        gk = fmaf(d1, sW1[128 + j], gk);
        gk = fmaf(d2, sW1[256 + j], gk);
        g[k] = gk * RM_LOG2E;
    }

    // Packed polynomial constants (loop-invariant, hoisted by ptxas)
    const unsigned long long A1 = rm_pack(RM_A1, RM_A1);
    const unsigned long long A2 = rm_pack(RM_A2, RM_A2);
    const unsigned long long A3 = rm_pack(RM_A3, RM_A3);
    const unsigned long long A4 = rm_pack(RM_A4, RM_A4);
    const unsigned long long A5 = rm_pack(RM_A5, RM_A5);

    const float b2v = sB2;
    int niter = *n_iter_p;
    if (niter < 0 || niter > 4096) niter = 20;   // defensive vs dtype mismatch

    const unsigned long long* __restrict__ w2pk =
        (const unsigned long long*)sW2p2;

    float alpha = 0.0f;
    for (int it = 0; it < niter; ++it) {
        unsigned long long acc2 = 0ull;          // {0.0f, 0.0f}
        #pragma unroll
        for (int p = 0; p < 16; ++p) {
            const float2 cw = sCp2[p * 4 + sub];
            const unsigned long long w2p = w2pk[p * 4 + sub];

            const float ya = fmaf(alpha, g[2*p    ], cw.x);   // y = x*log2e
            const float yb = fmaf(alpha, g[2*p + 1], cw.y);

            const float ea = rm_ex2(-fabsf(ya));              // 2^{-|y|}
            const float eb = rm_ex2(-fabsf(yb));

            // l = log2(1+e), degree-5 Horner, 2-wide
            const unsigned long long e2 = rm_pack(ea, eb);
            unsigned long long t = rm_fma2(e2, A5, A4);
            t = rm_fma2(t, e2, A3);
            t = rm_fma2(t, e2, A2);
            t = rm_fma2(t, e2, A1);
            t = rm_mul2(t, e2);                               // l2

            const unsigned long long m2 =
                rm_pack(fmaxf(ya, 0.0f), fmaxf(yb, 0.0f));
            t = rm_add2(t, m2);                               // h2 = softplus/ln2
            acc2 = rm_fma2(t, w2p, acc2);                     // * (W2*ln2)
        }
        float alo, ahi; rm_unpack(acc2, alo, ahi);
        float acc = alo + ahi;
        acc += __shfl_xor_sync(0xFFFFFFFFu, acc, 1);
        acc += __shfl_xor_sync(0xFFFFFFFFu, acc, 2);

        const float s   = acc + b2v;                          // sdf(x[1:])
        const float a   = fabsf(s);
        const float x0  = alpha * rn0;                        // x[0]
        const float ext = fmaxf(fmaxf(s, x0 - a), -(a + x0));
        alpha -= ext;
    }

    if (sub < 3) {
        const float dv = (sub == 0) ? d0 : (sub == 1 ? d1 : d2);
        out[ray * 3 + sub] = fmaf(alpha, dv, sPivot[sub]);
    }
}

extern "C" void kernel_launch(void* const* d_in, const int* in_sizes, int n_in,
                              void* d_out, int out_size)
{
    const float4* r     = (const float4*)d_in[0];   // (N, 4)
    const float*  pivot = (const float*)d_in[1];    // (1, 3)
    const float*  W1    = (const float*)d_in[2];    // (3, 128)
    const float*  b1    = (const float*)d_in[3];    // (128,)
    const float*  W2    = (const float*)d_in[4];    // (128, 1)
    const float*  b2    = (const float*)d_in[5];    // (1,)
    const int*    nit   = (const int*)d_in[6];      // scalar

    const int n_rays = in_sizes[0] / 4;
    float* out = (float*)d_out;                     // (N, 3)

    const int threads = 256;
    const int total   = n_rays * 4;
    const int blocks  = (total + threads - 1) / threads;
    rm_kernel<<<blocks, threads>>>(r, pivot, W1, b1, W2, b2, nit, out, n_rays);
}